// round 13
// baseline (speedup 1.0000x reference)
#include <cuda_runtime.h>
#include <cuda_bf16.h>

#define NHEADS 512
#define NK     64
#define SEQ    2048
#define NFFT   4096
#define NB     16
#define PITCH  272   // FFT transpose pitch: 16*17, conflict-free both patterns
#define TP     68    // T-matrix pitch: banks 4*uu+p distinct within warp

typedef unsigned long long ull;

// Scratch (static __device__ — no allocation)
__device__ float d_f[NHEADS * SEQ];
__device__ ull   d_Fhat[NHEADS * NFFT];   // packed complex, layout [h][q*256+t]

// ---------------------------------------------------------------------------
// Packed f32x2 complex helpers (value = ull, lo 32b = re, hi 32b = im)
// ---------------------------------------------------------------------------
__device__ __forceinline__ ull pk2(float x, float y) {
    ull r; asm("mov.b64 %0, {%1, %2};" : "=l"(r) : "f"(x), "f"(y)); return r;
}
__device__ __forceinline__ void unpk2(ull a, float& x, float& y) {
    asm("mov.b64 {%0, %1}, %2;" : "=f"(x), "=f"(y) : "l"(a));
}
__device__ __forceinline__ ull padd(ull a, ull b) {
    ull r; asm("add.rn.f32x2 %0, %1, %2;" : "=l"(r) : "l"(a), "l"(b)); return r;
}
__device__ __forceinline__ ull psub(ull a, ull b) {   // a - b via fma(b, -1, a)
    const ull m1 = 0xBF800000BF800000ULL;
    ull r; asm("fma.rn.f32x2 %0, %1, %2, %3;" : "=l"(r) : "l"(b), "l"(m1), "l"(a)); return r;
}
__device__ __forceinline__ float fneg(float x) {
    return __int_as_float(__float_as_int(x) ^ 0x80000000);
}
template<int INV>
__device__ __forceinline__ ull pmulj(ull a) {
    float x, y; unpk2(a, x, y);
    return INV ? pk2(fneg(y), x) : pk2(y, fneg(x));
}
__device__ __forceinline__ ull pcmulf(ull a, float wx, float wy) {
    float x, y; unpk2(a, x, y);
    return pk2(fmaf(x, wx, -(y * wy)), fmaf(x, wy, y * wx));
}

template<int INV>
__device__ __forceinline__ void bfly4p(ull& x0, ull& x1, ull& x2, ull& x3) {
    ull ac = padd(x0, x2), amc = psub(x0, x2);
    ull bd = padd(x1, x3), bmd = psub(x1, x3);
    ull jb = pmulj<INV>(bmd);
    x0 = padd(ac, bd);  x2 = psub(ac, bd);
    x1 = padd(amc, jb); x3 = psub(amc, jb);
}

// half-output butterfly: only out0/out1 produced
template<int INV>
__device__ __forceinline__ void bfly4p_half(ull& x0, ull& x1, ull x2, ull x3) {
    ull ac = padd(x0, x2), amc = psub(x0, x2);
    ull bd = padd(x1, x3), bmd = psub(x1, x3);
    ull jb = pmulj<INV>(bmd);
    x0 = padd(ac, bd);
    x1 = padd(amc, jb);
}

template<int INV>
__device__ __forceinline__ void tw16(ull* u) {
    const float C1 = 0.9238795325112867f, S1 = 0.3826834323650898f, R = 0.7071067811865476f;
    const float s = INV ? 1.0f : -1.0f;
    u[5]  = pcmulf(u[5],   C1,  s * S1);
    u[6]  = pcmulf(u[6],    R,  s * R);
    u[7]  = pcmulf(u[7],   S1,  s * C1);
    u[9]  = pcmulf(u[9],    R,  s * R);
    u[10] = pmulj<INV>(u[10]);
    u[11] = pcmulf(u[11],  -R,  s * R);
    u[13] = pcmulf(u[13],  S1,  s * C1);
    u[14] = pcmulf(u[14],  -R,  s * R);
    u[15] = pcmulf(u[15], -C1, -s * S1);
}

template<int INV>
__device__ __forceinline__ void dft16p(ull* x) {
    ull u[16];
    #pragma unroll
    for (int n1 = 0; n1 < 4; n1++) {
        ull a = x[n1], b = x[n1 + 4], c = x[n1 + 8], d = x[n1 + 12];
        bfly4p<INV>(a, b, c, d);
        u[n1 * 4 + 0] = a; u[n1 * 4 + 1] = b; u[n1 * 4 + 2] = c; u[n1 * 4 + 3] = d;
    }
    tw16<INV>(u);
    #pragma unroll
    for (int k1 = 0; k1 < 4; k1++) {
        ull a = u[k1], b = u[4 + k1], c = u[8 + k1], d = u[12 + k1];
        bfly4p<INV>(a, b, c, d);
        x[k1] = a; x[k1 + 4] = b; x[k1 + 8] = c; x[k1 + 12] = d;
    }
}

// Inverse 16-pt DFT producing only outputs 0..7 (final inv stage).
__device__ __forceinline__ void dft16p_half(ull* x) {
    ull u[16];
    #pragma unroll
    for (int n1 = 0; n1 < 4; n1++) {
        ull a = x[n1], b = x[n1 + 4], c = x[n1 + 8], d = x[n1 + 12];
        bfly4p<1>(a, b, c, d);
        u[n1 * 4 + 0] = a; u[n1 * 4 + 1] = b; u[n1 * 4 + 2] = c; u[n1 * 4 + 3] = d;
    }
    tw16<1>(u);
    #pragma unroll
    for (int k1 = 0; k1 < 4; k1++) {
        ull a = u[k1], b = u[4 + k1];
        bfly4p_half<1>(a, b, u[8 + k1], u[12 + k1]);
        x[k1] = a; x[k1 + 4] = b;
    }
}

// Forward 16-pt DFT with x[8..15] == 0 (only x[0..7] read; all 16 written).
__device__ __forceinline__ void dft16ph(ull* x) {
    ull u[16];
    #pragma unroll
    for (int n1 = 0; n1 < 4; n1++) {
        ull a = x[n1], b = x[n1 + 4];      // c = d = 0
        ull jb = pmulj<0>(b);
        u[n1 * 4 + 0] = padd(a, b);
        u[n1 * 4 + 2] = psub(a, b);
        u[n1 * 4 + 1] = padd(a, jb);
        u[n1 * 4 + 3] = psub(a, jb);
    }
    tw16<0>(u);
    #pragma unroll
    for (int k1 = 0; k1 < 4; k1++) {
        ull a = u[k1], b = u[4 + k1], c = u[8 + k1], d = u[12 + k1];
        bfly4p<0>(a, b, c, d);
        x[k1] = a; x[k1 + 4] = b; x[k1 + 8] = c; x[k1 + 12] = d;
    }
}

__device__ __forceinline__ void twchain(ull* r, float wx, float wy) {
    float px = wx, py = wy;
    #pragma unroll
    for (int q = 1; q < 16; q++) {
        r[q] = pcmulf(r[q], px, py);
        float nx = px * wx - py * wy;
        float ny = px * wy + py * wx;
        px = nx; py = ny;
    }
}

#define ANG1 (-1.5339807878856412e-3f)   // -2*pi/4096
#define ANG2 (-2.4543692606170259e-2f)   // -2*pi/256

// ---------------------------------------------------------------------------
// N=4096 radix-16 FFT, 256 threads, 16 packed complex in registers/thread.
// ---------------------------------------------------------------------------
__device__ __forceinline__ void fft4096_fwd(ull* r, ull* sh, int t) {
    const int o = t & 15, b = t >> 4;
    dft16ph(r);
    { float sy, cx; __sincosf(ANG1 * (float)t, &sy, &cx); twchain(r, cx, sy); }
    #pragma unroll
    for (int q = 0; q < 16; q++) sh[PITCH * q + t] = r[q];
    __syncthreads();
    #pragma unroll
    for (int m = 0; m < 16; m++) r[m] = sh[PITCH * b + 16 * m + o];
    dft16p<0>(r);
    { float sy, cx; __sincosf(ANG2 * (float)o, &sy, &cx); twchain(r, cx, sy); }
    __syncthreads();
    #pragma unroll
    for (int q = 0; q < 16; q++) sh[PITCH * b + 17 * q + o] = r[q];
    __syncthreads();
    #pragma unroll
    for (int j = 0; j < 16; j++) r[j] = sh[PITCH * b + 17 * o + j];
    dft16p<0>(r);
}

__device__ __forceinline__ void fft4096_inv(ull* r, ull* sh, int t) {
    const int o = t & 15, b = t >> 4;
    dft16p<1>(r);
    __syncthreads();
    #pragma unroll
    for (int j = 0; j < 16; j++) sh[PITCH * b + 17 * o + j] = r[j];
    __syncthreads();
    #pragma unroll
    for (int q = 0; q < 16; q++) r[q] = sh[PITCH * b + 17 * q + o];
    { float sy, cx; __sincosf(-ANG2 * (float)o, &sy, &cx); twchain(r, cx, sy); }
    dft16p<1>(r);
    __syncthreads();
    #pragma unroll
    for (int m = 0; m < 16; m++) sh[PITCH * b + 16 * m + o] = r[m];
    __syncthreads();
    #pragma unroll
    for (int q = 0; q < 16; q++) r[q] = sh[PITCH * q + t];
    { float sy, cx; __sincosf(-ANG1 * (float)t, &sy, &cx); twchain(r, cx, sy); }
    dft16p_half(r);
}

// ---------------------------------------------------------------------------
// K1: filter — bootstrap h_0..63 (warp doubling, validated R6), build the
// 64-step propagator T[u][j] = sum_v h_{u-1-v} w_{v+j} fully in parallel,
// then 31 single-dot chunk matvecs: a_{63+64m+u} = sum_j T[u][j] a_{63+64m-j}.
// Phase C: f_t = sum_i g_i a_{t-i} -> d_f  (1/NFFT folded into g).
// hb has a 64-slot zero low pad: T-build reads hb[64 + um1 - v], v <= 63.
// ---------------------------------------------------------------------------
__global__ __launch_bounds__(256) void filter_kernel(const float* __restrict__ kin) {
    __shared__ float sw[128];          // w padded: sw[64..127] = 0
    __shared__ float sg[64], skn[64], sP[64], spart[2];
    __shared__ float hb[160];          // hb[64+t] = h_t (t<64); hb[0..63] = 0
    __shared__ float po[64];           // bootstrap oldc, low pad 0
    __shared__ float sT[64 * TP];      // T[u][j] at sT[(u-1)*TP + j]
    __shared__ float sa[64 + SEQ];     // sa[64+t] = a_t = h_t ; sa[0..63] = 0

    const int tid = threadIdx.x;
    const int hh  = blockIdx.x;
    const int uu  = tid >> 2;          // 0..63  (chunk output row u = uu+1)
    const int p   = tid & 3;           // partial lane

    // zero pads
    if (tid < 128) sw[tid] = 0.f;
    if (tid < 160) hb[tid] = 0.f;
    if (tid < 64)  { po[tid] = 0.f; sa[tid] = 0.f; }

    // ---- prep: kn, P, w, g (threads 0..63)
    float kv = 0.f;
    if (tid < 64) {
        kv = kin[hh * NK + tid];
        float kc = fminf(fmaxf(kv, 0.0625f), 1.0f);
        float v = kc;
        #pragma unroll
        for (int o = 16; o; o >>= 1) v += __shfl_xor_sync(0xffffffffu, v, o);
        if ((tid & 31) == 0) spart[tid >> 5] = v;
        skn[tid] = kc;
    }
    __syncthreads();
    if (tid < 64) skn[tid] = skn[tid] / (spart[0] + spart[1]);
    __syncthreads();
    if (tid == 0) {
        float pr = 1.0f;
        for (int j = 0; j < 64; j++) {
            sP[j] = pr;
            if (j < 63) pr *= 1.0f / (1.0f + skn[j]);
        }
        hb[64] = 1.0f;   // h_0
    }
    __syncthreads();
    if (tid < 64) {
        float kn = skn[tid];
        float m0 = (tid < 63) ? kn / (1.0f + kn) : 1.0f;
        sw[tid] = m0 * sP[tid];
        sg[tid] = kv * sP[tid] * (1.0f / NFFT);
    }
    __syncthreads();

    // ---- bootstrap h_1..63 (warp 0 doubling; R6-validated, offsets +64)
    if (tid < 32) {
        const int rr = tid;
        #pragma unroll
        for (int s = 1; s <= 32; s <<= 1) {
            float oc = 0.f;
            if (rr < s) {
                #pragma unroll
                for (int m = 0; m < 32; m++)
                    oc += sw[rr + m] * hb[64 + s - 1 - m];
                po[32 + rr] = oc;
            }
            __syncwarp();
            if (rr < s) {
                float nv = 0.f;
                #pragma unroll
                for (int d = 0; d < 32; d++)
                    nv += hb[64 + d] * po[32 + rr - d];
                hb[64 + s + rr] = nv;
            }
            __syncwarp();
        }
    }
    __syncthreads();

    // seed sa with h_0..63
    if (tid < 64) sa[64 + tid] = hb[64 + tid];

    // ---- build T in parallel: 16 outputs per thread, fixed 64-tap dots.
    // o = seg*256 + tid ; u-1 = o>>6 ; j = o&63.
    #pragma unroll
    for (int seg = 0; seg < 16; seg++) {
        const int o   = seg * 256 + tid;
        const int um1 = o >> 6;
        const int j   = o & 63;
        const float* hh_ = &hb[64 + um1];     // h_{u-1-v} at hh_[-v]; pad -> 0
        const float* ww  = &sw[j];            // w_{v+j}  at ww[v] (padded)
        float a0 = 0.f, a1 = 0.f, a2 = 0.f, a3 = 0.f;
        #pragma unroll
        for (int v = 0; v < 64; v += 4) {
            a0 += hh_[-v - 0] * ww[v + 0];
            a1 += hh_[-v - 1] * ww[v + 1];
            a2 += hh_[-v - 2] * ww[v + 2];
            a3 += hh_[-v - 3] * ww[v + 3];
        }
        sT[um1 * TP + j] = (a0 + a1) + (a2 + a3);
    }
    __syncthreads();

    // register taps for chunk matvec: thread (uu, p) covers j = p + 4j'
    float treg[16];
    #pragma unroll
    for (int j2 = 0; j2 < 16; j2++) treg[j2] = sT[uu * TP + p + 4 * j2];

    // ---- 31 chunks: one dot each
    for (int m = 0; m < 31; m++) {
        const int top = 63 + 64 * m;
        const float* ab = &sa[64 + top - p];   // a_{top-p-4j'} at ab[-4j']
        float v0 = 0.f, v1 = 0.f;
        #pragma unroll
        for (int j2 = 0; j2 < 16; j2 += 2) {
            v0 += treg[j2 + 0] * ab[-4 * (j2 + 0)];
            v1 += treg[j2 + 1] * ab[-4 * (j2 + 1)];
        }
        float v = v0 + v1;
        v += __shfl_xor_sync(0xffffffffu, v, 1);
        v += __shfl_xor_sync(0xffffffffu, v, 2);
        if (p == 0) sa[64 + top + 1 + uu] = v;   // a_{64m+64+uu}
        __syncthreads();
    }

    // ---- phase C: f_t = sum_i g_i a_{t-i} -> d_f (coalesced)
    #pragma unroll
    for (int q = 0; q < 8; q++) {
        const int t = tid + 256 * q;
        const float* hbp = &sa[64 + t];
        float a0 = 0.f, a1 = 0.f, a2 = 0.f, a3 = 0.f;
        #pragma unroll
        for (int i = 0; i < 64; i += 4) {
            a0 += sg[i + 0] * hbp[-i - 0];
            a1 += sg[i + 1] * hbp[-i - 1];
            a2 += sg[i + 2] * hbp[-i - 2];
            a3 += sg[i + 3] * hbp[-i - 3];
        }
        d_f[hh * SEQ + t] = (a0 + a1) + (a2 + a3);
    }
}

// ---------------------------------------------------------------------------
// K2: filter spectrum (packed), layout [h][q*256+t]; 1/N folded into d_f.
// ---------------------------------------------------------------------------
__global__ __launch_bounds__(256) void fft_filter_kernel() {
    __shared__ ull exch[16 * PITCH];
    ull r[16];
    const int t = threadIdx.x, h = blockIdx.x;

    #pragma unroll
    for (int q = 0; q < 8; q++)
        r[q] = pk2(d_f[h * SEQ + t + 256 * q], 0.f);

    fft4096_fwd(r, exch, t);

    #pragma unroll
    for (int q = 0; q < 16; q++)
        d_Fhat[(size_t)h * NFFT + q * 256 + t] = r[q];
}

// ---------------------------------------------------------------------------
// K3: FFT convolution, two batches packed per complex FFT.
// ---------------------------------------------------------------------------
__global__ __launch_bounds__(256, 4) void conv_kernel(const float* __restrict__ u,
                                                      float* __restrict__ y) {
    __shared__ ull exch[16 * PITCH];
    ull r[16];
    const int t  = threadIdx.x;
    const int h  = blockIdx.y;
    const int bp = blockIdx.x;
    const float* u0 = u + ((size_t)(2 * bp) * NHEADS + h) * SEQ;
    const float* u1 = u0 + (size_t)NHEADS * SEQ;

    #pragma unroll
    for (int q = 0; q < 8; q++) {
        int idx = t + 256 * q;
        r[q] = pk2(__ldg(&u0[idx]), __ldg(&u1[idx]));
    }

    fft4096_fwd(r, exch, t);

    const ull* Fh = d_Fhat + (size_t)h * NFFT;
    #pragma unroll
    for (int q = 0; q < 16; q++) {
        float fx, fy; unpk2(__ldg(&Fh[q * 256 + t]), fx, fy);
        r[q] = pcmulf(r[q], fx, fy);
    }

    fft4096_inv(r, exch, t);

    float* y0 = y + ((size_t)(2 * bp) * NHEADS + h) * SEQ;
    float* y1 = y0 + (size_t)NHEADS * SEQ;
    #pragma unroll
    for (int m = 0; m < 8; m++) {
        int idx = t + 256 * m;
        float a, b; unpk2(r[m], a, b);
        y0[idx] = a;
        y1[idx] = b;
    }
}

// ---------------------------------------------------------------------------
extern "C" void kernel_launch(void* const* d_in, const int* in_sizes, int n_in,
                              void* d_out, int out_size) {
    const float* u = (const float*)d_in[0];
    const float* k = (const float*)d_in[1];
    if (n_in >= 2 && in_sizes[0] < in_sizes[1]) {
        const float* t = u; u = k; k = t;
    }
    float* y = (float*)d_out;

    filter_kernel<<<NHEADS, 256>>>(k);
    fft_filter_kernel<<<NHEADS, 256>>>();
    conv_kernel<<<dim3(NB / 2, NHEADS), 256>>>(u, y);
}

// round 14
// speedup vs baseline: 1.3724x; 1.3724x over previous
#include <cuda_runtime.h>
#include <cuda_bf16.h>

#define NHEADS 512
#define NK     64
#define SEQ    2048
#define NFFT   4096
#define NB     16
#define PITCH  272   // FFT transpose pitch: 16*17, conflict-free both patterns
#define TP     65    // T-matrix pitch (odd => row-wise reads conflict-free)

typedef unsigned long long ull;

// Scratch (static __device__ — no allocation)
__device__ float d_f[NHEADS * SEQ];
__device__ ull   d_Fhat[NHEADS * NFFT];   // packed complex, layout [h][q*256+t]

// ---------------------------------------------------------------------------
// Packed f32x2 complex helpers (value = ull, lo 32b = re, hi 32b = im)
// ---------------------------------------------------------------------------
__device__ __forceinline__ ull pk2(float x, float y) {
    ull r; asm("mov.b64 %0, {%1, %2};" : "=l"(r) : "f"(x), "f"(y)); return r;
}
__device__ __forceinline__ void unpk2(ull a, float& x, float& y) {
    asm("mov.b64 {%0, %1}, %2;" : "=f"(x), "=f"(y) : "l"(a));
}
__device__ __forceinline__ ull padd(ull a, ull b) {
    ull r; asm("add.rn.f32x2 %0, %1, %2;" : "=l"(r) : "l"(a), "l"(b)); return r;
}
__device__ __forceinline__ ull psub(ull a, ull b) {   // a - b via fma(b, -1, a)
    const ull m1 = 0xBF800000BF800000ULL;
    ull r; asm("fma.rn.f32x2 %0, %1, %2, %3;" : "=l"(r) : "l"(b), "l"(m1), "l"(a)); return r;
}
__device__ __forceinline__ float fneg(float x) {
    return __int_as_float(__float_as_int(x) ^ 0x80000000);
}
template<int INV>
__device__ __forceinline__ ull pmulj(ull a) {
    float x, y; unpk2(a, x, y);
    return INV ? pk2(fneg(y), x) : pk2(y, fneg(x));
}
__device__ __forceinline__ ull pcmulf(ull a, float wx, float wy) {
    float x, y; unpk2(a, x, y);
    return pk2(fmaf(x, wx, -(y * wy)), fmaf(x, wy, y * wx));
}

template<int INV>
__device__ __forceinline__ void bfly4p(ull& x0, ull& x1, ull& x2, ull& x3) {
    ull ac = padd(x0, x2), amc = psub(x0, x2);
    ull bd = padd(x1, x3), bmd = psub(x1, x3);
    ull jb = pmulj<INV>(bmd);
    x0 = padd(ac, bd);  x2 = psub(ac, bd);
    x1 = padd(amc, jb); x3 = psub(amc, jb);
}

// half-output butterfly: only out0/out1 produced
template<int INV>
__device__ __forceinline__ void bfly4p_half(ull& x0, ull& x1, ull x2, ull x3) {
    ull ac = padd(x0, x2), amc = psub(x0, x2);
    ull bd = padd(x1, x3), bmd = psub(x1, x3);
    ull jb = pmulj<INV>(bmd);
    x0 = padd(ac, bd);
    x1 = padd(amc, jb);
}

template<int INV>
__device__ __forceinline__ void tw16(ull* u) {
    const float C1 = 0.9238795325112867f, S1 = 0.3826834323650898f, R = 0.7071067811865476f;
    const float s = INV ? 1.0f : -1.0f;
    u[5]  = pcmulf(u[5],   C1,  s * S1);
    u[6]  = pcmulf(u[6],    R,  s * R);
    u[7]  = pcmulf(u[7],   S1,  s * C1);
    u[9]  = pcmulf(u[9],    R,  s * R);
    u[10] = pmulj<INV>(u[10]);
    u[11] = pcmulf(u[11],  -R,  s * R);
    u[13] = pcmulf(u[13],  S1,  s * C1);
    u[14] = pcmulf(u[14],  -R,  s * R);
    u[15] = pcmulf(u[15], -C1, -s * S1);
}

template<int INV>
__device__ __forceinline__ void dft16p(ull* x) {
    ull u[16];
    #pragma unroll
    for (int n1 = 0; n1 < 4; n1++) {
        ull a = x[n1], b = x[n1 + 4], c = x[n1 + 8], d = x[n1 + 12];
        bfly4p<INV>(a, b, c, d);
        u[n1 * 4 + 0] = a; u[n1 * 4 + 1] = b; u[n1 * 4 + 2] = c; u[n1 * 4 + 3] = d;
    }
    tw16<INV>(u);
    #pragma unroll
    for (int k1 = 0; k1 < 4; k1++) {
        ull a = u[k1], b = u[4 + k1], c = u[8 + k1], d = u[12 + k1];
        bfly4p<INV>(a, b, c, d);
        x[k1] = a; x[k1 + 4] = b; x[k1 + 8] = c; x[k1 + 12] = d;
    }
}

// Inverse 16-pt DFT producing only outputs 0..7 (final inv stage).
__device__ __forceinline__ void dft16p_half(ull* x) {
    ull u[16];
    #pragma unroll
    for (int n1 = 0; n1 < 4; n1++) {
        ull a = x[n1], b = x[n1 + 4], c = x[n1 + 8], d = x[n1 + 12];
        bfly4p<1>(a, b, c, d);
        u[n1 * 4 + 0] = a; u[n1 * 4 + 1] = b; u[n1 * 4 + 2] = c; u[n1 * 4 + 3] = d;
    }
    tw16<1>(u);
    #pragma unroll
    for (int k1 = 0; k1 < 4; k1++) {
        ull a = u[k1], b = u[4 + k1];
        bfly4p_half<1>(a, b, u[8 + k1], u[12 + k1]);
        x[k1] = a; x[k1 + 4] = b;
    }
}

// Forward 16-pt DFT with x[8..15] == 0 (only x[0..7] read; all 16 written).
__device__ __forceinline__ void dft16ph(ull* x) {
    ull u[16];
    #pragma unroll
    for (int n1 = 0; n1 < 4; n1++) {
        ull a = x[n1], b = x[n1 + 4];      // c = d = 0
        ull jb = pmulj<0>(b);
        u[n1 * 4 + 0] = padd(a, b);
        u[n1 * 4 + 2] = psub(a, b);
        u[n1 * 4 + 1] = padd(a, jb);
        u[n1 * 4 + 3] = psub(a, jb);
    }
    tw16<0>(u);
    #pragma unroll
    for (int k1 = 0; k1 < 4; k1++) {
        ull a = u[k1], b = u[4 + k1], c = u[8 + k1], d = u[12 + k1];
        bfly4p<0>(a, b, c, d);
        x[k1] = a; x[k1 + 4] = b; x[k1 + 8] = c; x[k1 + 12] = d;
    }
}

__device__ __forceinline__ void twchain(ull* r, float wx, float wy) {
    float px = wx, py = wy;
    #pragma unroll
    for (int q = 1; q < 16; q++) {
        r[q] = pcmulf(r[q], px, py);
        float nx = px * wx - py * wy;
        float ny = px * wy + py * wx;
        px = nx; py = ny;
    }
}

#define ANG1 (-1.5339807878856412e-3f)   // -2*pi/4096
#define ANG2 (-2.4543692606170259e-2f)   // -2*pi/256

// ---------------------------------------------------------------------------
// N=4096 radix-16 FFT, 256 threads, 16 packed complex in registers/thread.
// ---------------------------------------------------------------------------
__device__ __forceinline__ void fft4096_fwd(ull* r, ull* sh, int t) {
    const int o = t & 15, b = t >> 4;
    dft16ph(r);
    { float sy, cx; __sincosf(ANG1 * (float)t, &sy, &cx); twchain(r, cx, sy); }
    #pragma unroll
    for (int q = 0; q < 16; q++) sh[PITCH * q + t] = r[q];
    __syncthreads();
    #pragma unroll
    for (int m = 0; m < 16; m++) r[m] = sh[PITCH * b + 16 * m + o];
    dft16p<0>(r);
    { float sy, cx; __sincosf(ANG2 * (float)o, &sy, &cx); twchain(r, cx, sy); }
    __syncthreads();
    #pragma unroll
    for (int q = 0; q < 16; q++) sh[PITCH * b + 17 * q + o] = r[q];
    __syncthreads();
    #pragma unroll
    for (int j = 0; j < 16; j++) r[j] = sh[PITCH * b + 17 * o + j];
    dft16p<0>(r);
}

__device__ __forceinline__ void fft4096_inv(ull* r, ull* sh, int t) {
    const int o = t & 15, b = t >> 4;
    dft16p<1>(r);
    __syncthreads();
    #pragma unroll
    for (int j = 0; j < 16; j++) sh[PITCH * b + 17 * o + j] = r[j];
    __syncthreads();
    #pragma unroll
    for (int q = 0; q < 16; q++) r[q] = sh[PITCH * b + 17 * q + o];
    { float sy, cx; __sincosf(-ANG2 * (float)o, &sy, &cx); twchain(r, cx, sy); }
    dft16p<1>(r);
    __syncthreads();
    #pragma unroll
    for (int m = 0; m < 16; m++) sh[PITCH * b + 16 * m + o] = r[m];
    __syncthreads();
    #pragma unroll
    for (int q = 0; q < 16; q++) r[q] = sh[PITCH * q + t];
    { float sy, cx; __sincosf(-ANG1 * (float)t, &sy, &cx); twchain(r, cx, sy); }
    dft16p_half(r);
}

// ---------------------------------------------------------------------------
// K1: filter.  Bootstrap h_0..63 (warp doubling, validated), parallel T-build
// T[u][j] = sum_v h_{u-1-v} w_{v+j} (u = 1..64, validated R13), then a
// SINGLE-WARP chunk loop (32 lanes x 2 rows, syncwarp only):
//   a_{top+u} = sum_j T[u][j] a_{top-j},  top = 63 + 64m, m = 0..30.
// Phase C: f_t = sum_i g_i a_{t-i} -> d_f  (1/NFFT folded into g).
// ---------------------------------------------------------------------------
__global__ __launch_bounds__(256) void filter_kernel(const float* __restrict__ kin) {
    __shared__ float sw[128];          // w padded: sw[64..127] = 0
    __shared__ float sg[64], skn[64], sP[64], spart[2];
    __shared__ float hb[160];          // hb[64+t] = h_t (t<64); hb[0..63] = 0
    __shared__ float po[64];           // bootstrap oldc, low pad 0
    __shared__ float sT[64 * TP];      // T[u][j] at sT[(u-1)*TP + j]
    __shared__ float sa[64 + SEQ];     // sa[64+t] = a_t = h_t ; sa[0..63] = 0

    const int tid = threadIdx.x;
    const int hh  = blockIdx.x;

    // zero pads
    if (tid < 128) sw[tid] = 0.f;
    if (tid < 160) hb[tid] = 0.f;
    if (tid < 64)  { po[tid] = 0.f; sa[tid] = 0.f; }

    // ---- prep: kn, P, w, g (threads 0..63)
    float kv = 0.f;
    if (tid < 64) {
        kv = kin[hh * NK + tid];
        float kc = fminf(fmaxf(kv, 0.0625f), 1.0f);
        float v = kc;
        #pragma unroll
        for (int o = 16; o; o >>= 1) v += __shfl_xor_sync(0xffffffffu, v, o);
        if ((tid & 31) == 0) spart[tid >> 5] = v;
        skn[tid] = kc;
    }
    __syncthreads();
    if (tid < 64) skn[tid] = skn[tid] / (spart[0] + spart[1]);
    __syncthreads();
    if (tid == 0) {
        float pr = 1.0f;
        for (int j = 0; j < 64; j++) {
            sP[j] = pr;
            if (j < 63) pr *= 1.0f / (1.0f + skn[j]);
        }
        hb[64] = 1.0f;   // h_0
    }
    __syncthreads();
    if (tid < 64) {
        float kn = skn[tid];
        float m0 = (tid < 63) ? kn / (1.0f + kn) : 1.0f;
        sw[tid] = m0 * sP[tid];
        sg[tid] = kv * sP[tid] * (1.0f / NFFT);
    }
    __syncthreads();

    // ---- bootstrap h_1..63 (warp 0 doubling; validated)
    if (tid < 32) {
        const int rr = tid;
        #pragma unroll
        for (int s = 1; s <= 32; s <<= 1) {
            float oc = 0.f;
            if (rr < s) {
                #pragma unroll
                for (int m = 0; m < 32; m++)
                    oc += sw[rr + m] * hb[64 + s - 1 - m];
                po[32 + rr] = oc;
            }
            __syncwarp();
            if (rr < s) {
                float nv = 0.f;
                #pragma unroll
                for (int d = 0; d < 32; d++)
                    nv += hb[64 + d] * po[32 + rr - d];
                hb[64 + s + rr] = nv;
            }
            __syncwarp();
        }
    }
    __syncthreads();

    // seed sa with h_0..63
    if (tid < 64) sa[64 + tid] = hb[64 + tid];

    // ---- parallel T-build: 16 entries per thread, fixed 64-tap dots.
    // o = seg*256 + tid ; u-1 = o>>6 ; j = o&63.  (validated R13; pad safe)
    #pragma unroll
    for (int seg = 0; seg < 16; seg++) {
        const int o   = seg * 256 + tid;
        const int um1 = o >> 6;
        const int j   = o & 63;
        const float* hh_ = &hb[64 + um1];     // h_{u-1-v} at hh_[-v]; pad -> 0
        const float* ww  = &sw[j];            // w_{v+j}  at ww[v] (padded)
        float a0 = 0.f, a1 = 0.f, a2 = 0.f, a3 = 0.f;
        #pragma unroll
        for (int v = 0; v < 64; v += 4) {
            a0 += hh_[-v - 0] * ww[v + 0];
            a1 += hh_[-v - 1] * ww[v + 1];
            a2 += hh_[-v - 2] * ww[v + 2];
            a3 += hh_[-v - 3] * ww[v + 3];
        }
        sT[um1 * TP + j] = (a0 + a1) + (a2 + a3);
    }
    __syncthreads();

    // ---- single-warp chunk loop: lanes own rows (tid, tid+32); no bar.sync
    if (tid < 32) {
        const float* row1 = &sT[tid * TP];           // u = tid+1
        const float* row2 = &sT[(tid + 32) * TP];    // u = tid+33
        for (int m = 0; m < 31; m++) {
            const int top = 63 + 64 * m;
            const float* ab = &sa[64 + top];          // a_{top-j} at ab[-j]
            float x0 = 0.f, x1 = 0.f, x2 = 0.f, x3 = 0.f;
            float y0 = 0.f, y1 = 0.f, y2 = 0.f, y3 = 0.f;
            #pragma unroll
            for (int j = 0; j < 64; j += 4) {
                float b0 = ab[-j - 0], b1 = ab[-j - 1];
                float b2 = ab[-j - 2], b3 = ab[-j - 3];
                x0 += row1[j + 0] * b0;  y0 += row2[j + 0] * b0;
                x1 += row1[j + 1] * b1;  y1 += row2[j + 1] * b1;
                x2 += row1[j + 2] * b2;  y2 += row2[j + 2] * b2;
                x3 += row1[j + 3] * b3;  y3 += row2[j + 3] * b3;
            }
            __syncwarp();
            sa[64 + top + 1 + tid]  = (x0 + x1) + (x2 + x3);   // a_{top+tid+1}
            sa[64 + top + 33 + tid] = (y0 + y1) + (y2 + y3);   // a_{top+tid+33}
            __syncwarp();
        }
    }
    __syncthreads();

    // ---- phase C: f_t = sum_i g_i a_{t-i} -> d_f (coalesced)
    #pragma unroll
    for (int q = 0; q < 8; q++) {
        const int t = tid + 256 * q;
        const float* hbp = &sa[64 + t];
        float a0 = 0.f, a1 = 0.f, a2 = 0.f, a3 = 0.f;
        #pragma unroll
        for (int i = 0; i < 64; i += 4) {
            a0 += sg[i + 0] * hbp[-i - 0];
            a1 += sg[i + 1] * hbp[-i - 1];
            a2 += sg[i + 2] * hbp[-i - 2];
            a3 += sg[i + 3] * hbp[-i - 3];
        }
        d_f[hh * SEQ + t] = (a0 + a1) + (a2 + a3);
    }
}

// ---------------------------------------------------------------------------
// K2: filter spectrum (packed), layout [h][q*256+t]; 1/N folded into d_f.
// ---------------------------------------------------------------------------
__global__ __launch_bounds__(256) void fft_filter_kernel() {
    __shared__ ull exch[16 * PITCH];
    ull r[16];
    const int t = threadIdx.x, h = blockIdx.x;

    #pragma unroll
    for (int q = 0; q < 8; q++)
        r[q] = pk2(d_f[h * SEQ + t + 256 * q], 0.f);

    fft4096_fwd(r, exch, t);

    #pragma unroll
    for (int q = 0; q < 16; q++)
        d_Fhat[(size_t)h * NFFT + q * 256 + t] = r[q];
}

// ---------------------------------------------------------------------------
// K3: FFT convolution, two batches packed per complex FFT.
// ---------------------------------------------------------------------------
__global__ __launch_bounds__(256, 4) void conv_kernel(const float* __restrict__ u,
                                                      float* __restrict__ y) {
    __shared__ ull exch[16 * PITCH];
    ull r[16];
    const int t  = threadIdx.x;
    const int h  = blockIdx.y;
    const int bp = blockIdx.x;
    const float* u0 = u + ((size_t)(2 * bp) * NHEADS + h) * SEQ;
    const float* u1 = u0 + (size_t)NHEADS * SEQ;

    #pragma unroll
    for (int q = 0; q < 8; q++) {
        int idx = t + 256 * q;
        r[q] = pk2(__ldg(&u0[idx]), __ldg(&u1[idx]));
    }

    fft4096_fwd(r, exch, t);

    const ull* Fh = d_Fhat + (size_t)h * NFFT;
    #pragma unroll
    for (int q = 0; q < 16; q++) {
        float fx, fy; unpk2(__ldg(&Fh[q * 256 + t]), fx, fy);
        r[q] = pcmulf(r[q], fx, fy);
    }

    fft4096_inv(r, exch, t);

    float* y0 = y + ((size_t)(2 * bp) * NHEADS + h) * SEQ;
    float* y1 = y0 + (size_t)NHEADS * SEQ;
    #pragma unroll
    for (int m = 0; m < 8; m++) {
        int idx = t + 256 * m;
        float a, b; unpk2(r[m], a, b);
        y0[idx] = a;
        y1[idx] = b;
    }
}

// ---------------------------------------------------------------------------
extern "C" void kernel_launch(void* const* d_in, const int* in_sizes, int n_in,
                              void* d_out, int out_size) {
    const float* u = (const float*)d_in[0];
    const float* k = (const float*)d_in[1];
    if (n_in >= 2 && in_sizes[0] < in_sizes[1]) {
        const float* t = u; u = k; k = t;
    }
    float* y = (float*)d_out;

    filter_kernel<<<NHEADS, 256>>>(k);
    fft_filter_kernel<<<NHEADS, 256>>>();
    conv_kernel<<<dim3(NB / 2, NHEADS), 256>>>(u, y);
}

// round 15
// speedup vs baseline: 1.8731x; 1.3648x over previous
#include <cuda_runtime.h>
#include <cuda_bf16.h>

#define NHEADS 512
#define NK     64
#define SEQ    2048
#define NFFT   4096
#define NB     16
#define PITCH  272   // FFT transpose pitch: 16*17, conflict-free both patterns

typedef unsigned long long ull;

// Scratch (static __device__ — no allocation)
__device__ float d_h[NHEADS * SEQ];       // impulse response per head
__device__ float d_g[NHEADS * NK];        // readout taps (1/NFFT folded)
__device__ ull   d_Fhat[NHEADS * NFFT];   // packed complex, layout [h][q*256+t]

// ---------------------------------------------------------------------------
// Packed f32x2 complex helpers (value = ull, lo 32b = re, hi 32b = im)
// ---------------------------------------------------------------------------
__device__ __forceinline__ ull pk2(float x, float y) {
    ull r; asm("mov.b64 %0, {%1, %2};" : "=l"(r) : "f"(x), "f"(y)); return r;
}
__device__ __forceinline__ void unpk2(ull a, float& x, float& y) {
    asm("mov.b64 {%0, %1}, %2;" : "=f"(x), "=f"(y) : "l"(a));
}
__device__ __forceinline__ ull padd(ull a, ull b) {
    ull r; asm("add.rn.f32x2 %0, %1, %2;" : "=l"(r) : "l"(a), "l"(b)); return r;
}
__device__ __forceinline__ ull psub(ull a, ull b) {   // a - b via fma(b, -1, a)
    const ull m1 = 0xBF800000BF800000ULL;
    ull r; asm("fma.rn.f32x2 %0, %1, %2, %3;" : "=l"(r) : "l"(b), "l"(m1), "l"(a)); return r;
}
__device__ __forceinline__ float fneg(float x) {
    return __int_as_float(__float_as_int(x) ^ 0x80000000);
}
template<int INV>
__device__ __forceinline__ ull pmulj(ull a) {
    float x, y; unpk2(a, x, y);
    return INV ? pk2(fneg(y), x) : pk2(y, fneg(x));
}
__device__ __forceinline__ ull pcmulf(ull a, float wx, float wy) {
    float x, y; unpk2(a, x, y);
    return pk2(fmaf(x, wx, -(y * wy)), fmaf(x, wy, y * wx));
}

template<int INV>
__device__ __forceinline__ void bfly4p(ull& x0, ull& x1, ull& x2, ull& x3) {
    ull ac = padd(x0, x2), amc = psub(x0, x2);
    ull bd = padd(x1, x3), bmd = psub(x1, x3);
    ull jb = pmulj<INV>(bmd);
    x0 = padd(ac, bd);  x2 = psub(ac, bd);
    x1 = padd(amc, jb); x3 = psub(amc, jb);
}

// half-output butterfly: only out0/out1 produced
template<int INV>
__device__ __forceinline__ void bfly4p_half(ull& x0, ull& x1, ull x2, ull x3) {
    ull ac = padd(x0, x2), amc = psub(x0, x2);
    ull bd = padd(x1, x3), bmd = psub(x1, x3);
    ull jb = pmulj<INV>(bmd);
    x0 = padd(ac, bd);
    x1 = padd(amc, jb);
}

template<int INV>
__device__ __forceinline__ void tw16(ull* u) {
    const float C1 = 0.9238795325112867f, S1 = 0.3826834323650898f, R = 0.7071067811865476f;
    const float s = INV ? 1.0f : -1.0f;
    u[5]  = pcmulf(u[5],   C1,  s * S1);
    u[6]  = pcmulf(u[6],    R,  s * R);
    u[7]  = pcmulf(u[7],   S1,  s * C1);
    u[9]  = pcmulf(u[9],    R,  s * R);
    u[10] = pmulj<INV>(u[10]);
    u[11] = pcmulf(u[11],  -R,  s * R);
    u[13] = pcmulf(u[13],  S1,  s * C1);
    u[14] = pcmulf(u[14],  -R,  s * R);
    u[15] = pcmulf(u[15], -C1, -s * S1);
}

template<int INV>
__device__ __forceinline__ void dft16p(ull* x) {
    ull u[16];
    #pragma unroll
    for (int n1 = 0; n1 < 4; n1++) {
        ull a = x[n1], b = x[n1 + 4], c = x[n1 + 8], d = x[n1 + 12];
        bfly4p<INV>(a, b, c, d);
        u[n1 * 4 + 0] = a; u[n1 * 4 + 1] = b; u[n1 * 4 + 2] = c; u[n1 * 4 + 3] = d;
    }
    tw16<INV>(u);
    #pragma unroll
    for (int k1 = 0; k1 < 4; k1++) {
        ull a = u[k1], b = u[4 + k1], c = u[8 + k1], d = u[12 + k1];
        bfly4p<INV>(a, b, c, d);
        x[k1] = a; x[k1 + 4] = b; x[k1 + 8] = c; x[k1 + 12] = d;
    }
}

// Inverse 16-pt DFT producing only outputs 0..7 (final inv stage).
__device__ __forceinline__ void dft16p_half(ull* x) {
    ull u[16];
    #pragma unroll
    for (int n1 = 0; n1 < 4; n1++) {
        ull a = x[n1], b = x[n1 + 4], c = x[n1 + 8], d = x[n1 + 12];
        bfly4p<1>(a, b, c, d);
        u[n1 * 4 + 0] = a; u[n1 * 4 + 1] = b; u[n1 * 4 + 2] = c; u[n1 * 4 + 3] = d;
    }
    tw16<1>(u);
    #pragma unroll
    for (int k1 = 0; k1 < 4; k1++) {
        ull a = u[k1], b = u[4 + k1];
        bfly4p_half<1>(a, b, u[8 + k1], u[12 + k1]);
        x[k1] = a; x[k1 + 4] = b;
    }
}

// Forward 16-pt DFT with x[8..15] == 0 (only x[0..7] read; all 16 written).
__device__ __forceinline__ void dft16ph(ull* x) {
    ull u[16];
    #pragma unroll
    for (int n1 = 0; n1 < 4; n1++) {
        ull a = x[n1], b = x[n1 + 4];      // c = d = 0
        ull jb = pmulj<0>(b);
        u[n1 * 4 + 0] = padd(a, b);
        u[n1 * 4 + 2] = psub(a, b);
        u[n1 * 4 + 1] = padd(a, jb);
        u[n1 * 4 + 3] = psub(a, jb);
    }
    tw16<0>(u);
    #pragma unroll
    for (int k1 = 0; k1 < 4; k1++) {
        ull a = u[k1], b = u[4 + k1], c = u[8 + k1], d = u[12 + k1];
        bfly4p<0>(a, b, c, d);
        x[k1] = a; x[k1 + 4] = b; x[k1 + 8] = c; x[k1 + 12] = d;
    }
}

__device__ __forceinline__ void twchain(ull* r, float wx, float wy) {
    float px = wx, py = wy;
    #pragma unroll
    for (int q = 1; q < 16; q++) {
        r[q] = pcmulf(r[q], px, py);
        float nx = px * wx - py * wy;
        float ny = px * wy + py * wx;
        px = nx; py = ny;
    }
}

#define ANG1 (-1.5339807878856412e-3f)   // -2*pi/4096
#define ANG2 (-2.4543692606170259e-2f)   // -2*pi/256

// ---------------------------------------------------------------------------
// N=4096 radix-16 FFT, 256 threads, 16 packed complex in registers/thread.
// ---------------------------------------------------------------------------
__device__ __forceinline__ void fft4096_fwd(ull* r, ull* sh, int t) {
    const int o = t & 15, b = t >> 4;
    dft16ph(r);
    { float sy, cx; __sincosf(ANG1 * (float)t, &sy, &cx); twchain(r, cx, sy); }
    #pragma unroll
    for (int q = 0; q < 16; q++) sh[PITCH * q + t] = r[q];
    __syncthreads();
    #pragma unroll
    for (int m = 0; m < 16; m++) r[m] = sh[PITCH * b + 16 * m + o];
    dft16p<0>(r);
    { float sy, cx; __sincosf(ANG2 * (float)o, &sy, &cx); twchain(r, cx, sy); }
    __syncthreads();
    #pragma unroll
    for (int q = 0; q < 16; q++) sh[PITCH * b + 17 * q + o] = r[q];
    __syncthreads();
    #pragma unroll
    for (int j = 0; j < 16; j++) r[j] = sh[PITCH * b + 17 * o + j];
    dft16p<0>(r);
}

__device__ __forceinline__ void fft4096_inv(ull* r, ull* sh, int t) {
    const int o = t & 15, b = t >> 4;
    dft16p<1>(r);
    __syncthreads();
    #pragma unroll
    for (int j = 0; j < 16; j++) sh[PITCH * b + 17 * o + j] = r[j];
    __syncthreads();
    #pragma unroll
    for (int q = 0; q < 16; q++) r[q] = sh[PITCH * b + 17 * q + o];
    { float sy, cx; __sincosf(-ANG2 * (float)o, &sy, &cx); twchain(r, cx, sy); }
    dft16p<1>(r);
    __syncthreads();
    #pragma unroll
    for (int m = 0; m < 16; m++) sh[PITCH * b + 16 * m + o] = r[m];
    __syncthreads();
    #pragma unroll
    for (int q = 0; q < 16; q++) r[q] = sh[PITCH * q + t];
    { float sy, cx; __sincosf(-ANG1 * (float)t, &sy, &cx); twchain(r, cx, sy); }
    dft16p_half(r);
}

// ---------------------------------------------------------------------------
// K1: impulse response by doubling (validated R10/R11 math, minimal work).
//   h_0 = 1;  h_t = sum_{i<64} w_i h_{t-1-i}
//   level s: c_m = sum_i w_i hp[s+m-1-i]  (zero frontier makes this exact)
//            h_{s+r} = sum_{m<64} c_m h_{r-m},  r = 0..s-1
// Warp bootstrap to h_63, block levels s=64..1024. Levels 512/1024 use a
// streaming-FIR (8 consecutive outputs/thread, 15-reg window per 8 taps).
// Writes h and g to global; phase C + FFT live in K2.
// ---------------------------------------------------------------------------
__global__ __launch_bounds__(256) void filter_kernel(const float* __restrict__ kin) {
    __shared__ float sw[128];          // w padded: sw[64..127] = 0
    __shared__ float sg[64], skn[64], sP[64], spart[2];
    __shared__ float po[64];           // bootstrap oldc, low pad 0
    __shared__ float OO[128];          // OO[64+m] = c_m ; OO[0..63] = 0
    __shared__ float hp[64 + SEQ];     // hp[64+t] = h_t ; hp[0..63] = 0

    const int tid = threadIdx.x;
    const int hh  = blockIdx.x;

    for (int i = tid; i < 64 + SEQ; i += 256) hp[i] = 0.f;
    if (tid < 128) { sw[tid] = 0.f; OO[tid] = 0.f; }
    if (tid < 64)  po[tid] = 0.f;

    // ---- prep: kn, P, w, g (threads 0..63)  [validated R13]
    float kv = 0.f;
    if (tid < 64) {
        kv = kin[hh * NK + tid];
        float kc = fminf(fmaxf(kv, 0.0625f), 1.0f);
        float v = kc;
        #pragma unroll
        for (int o = 16; o; o >>= 1) v += __shfl_xor_sync(0xffffffffu, v, o);
        if ((tid & 31) == 0) spart[tid >> 5] = v;
        skn[tid] = kc;
    }
    __syncthreads();
    if (tid < 64) skn[tid] = skn[tid] / (spart[0] + spart[1]);
    __syncthreads();
    if (tid == 0) {
        float pr = 1.0f;
        for (int j = 0; j < 64; j++) {
            sP[j] = pr;
            if (j < 63) pr *= 1.0f / (1.0f + skn[j]);
        }
        hp[64] = 1.0f;   // h_0
    }
    __syncthreads();
    if (tid < 64) {
        float kn = skn[tid];
        float m0 = (tid < 63) ? kn / (1.0f + kn) : 1.0f;
        sw[tid] = m0 * sP[tid];
        sg[tid] = kv * sP[tid] * (1.0f / NFFT);
    }
    __syncthreads();

    // ---- warp bootstrap h_1..63 (validated R13/R14; hp has 64-pad)
    if (tid < 32) {
        const int rr = tid;
        #pragma unroll
        for (int s = 1; s <= 32; s <<= 1) {
            float oc = 0.f;
            if (rr < s) {
                #pragma unroll
                for (int m = 0; m < 32; m++)
                    oc += sw[rr + m] * hp[64 + s - 1 - m];
                po[32 + rr] = oc;
            }
            __syncwarp();
            if (rr < s) {
                float nv = 0.f;
                #pragma unroll
                for (int d = 0; d < 32; d++)
                    nv += hp[64 + d] * po[32 + rr - d];
                hp[64 + s + rr] = nv;
            }
            __syncwarp();
        }
    }
    __syncthreads();

    // ---- block levels s = 64, 128, 256 (plain per-output; validated R10/R11)
    for (int s = 64; s <= 256; s <<= 1) {
        if (tid < 64) {
            const float* base = &hp[64 + s + tid - 1];
            float a0 = 0.f, a1 = 0.f, a2 = 0.f, a3 = 0.f;
            #pragma unroll
            for (int i = 0; i < 64; i += 4) {
                a0 += sw[i + 0] * base[-i - 0];
                a1 += sw[i + 1] * base[-i - 1];
                a2 += sw[i + 2] * base[-i - 2];
                a3 += sw[i + 3] * base[-i - 3];
            }
            OO[64 + tid] = (a0 + a1) + (a2 + a3);
        }
        __syncthreads();
        for (int r = tid; r < s; r += 256) {
            const float* hb = &hp[64 + r];
            float a0 = 0.f, a1 = 0.f, a2 = 0.f, a3 = 0.f;
            #pragma unroll
            for (int m = 0; m < 64; m += 4) {
                a0 += OO[64 + m + 0] * hb[-m - 0];
                a1 += OO[64 + m + 1] * hb[-m - 1];
                a2 += OO[64 + m + 2] * hb[-m - 2];
                a3 += OO[64 + m + 3] * hb[-m - 3];
            }
            hp[64 + s + r] = (a0 + a1) + (a2 + a3);
        }
        __syncthreads();
    }

    // ---- levels s = 512, 1024 (streaming FIR: 8 consecutive outputs/thread)
    for (int s = 512; s <= 1024; s <<= 1) {
        if (tid < 64) {
            const float* base = &hp[64 + s + tid - 1];
            float a0 = 0.f, a1 = 0.f, a2 = 0.f, a3 = 0.f;
            #pragma unroll
            for (int i = 0; i < 64; i += 4) {
                a0 += sw[i + 0] * base[-i - 0];
                a1 += sw[i + 1] * base[-i - 1];
                a2 += sw[i + 2] * base[-i - 2];
                a3 += sw[i + 3] * base[-i - 3];
            }
            OO[64 + tid] = (a0 + a1) + (a2 + a3);
        }
        __syncthreads();
        {
            const int r0 = tid * 8;
            if (r0 < s) {
                float acc[8];
                #pragma unroll
                for (int k = 0; k < 8; k++) acc[k] = 0.f;
                #pragma unroll
                for (int mc = 0; mc < 8; mc++) {
                    float w[15];
                    const int base = 64 + r0 - 8 * mc - 7;   // >= 1, pad-safe
                    #pragma unroll
                    for (int d = 0; d < 15; d++) w[d] = hp[base + d];
                    #pragma unroll
                    for (int j = 0; j < 8; j++) {
                        const float c = OO[64 + 8 * mc + j];
                        #pragma unroll
                        for (int k = 0; k < 8; k++)
                            acc[k] += c * w[7 + k - j];
                    }
                }
                #pragma unroll
                for (int k = 0; k < 8; k++)
                    hp[64 + s + r0 + k] = acc[k];
            }
        }
        __syncthreads();
    }

    // ---- write h, g to global (coalesced)
    #pragma unroll
    for (int q = 0; q < 8; q++)
        d_h[hh * SEQ + tid + 256 * q] = hp[64 + tid + 256 * q];
    if (tid < 64) d_g[hh * NK + tid] = sg[tid];
}

// ---------------------------------------------------------------------------
// K2: phase C (f = g conv h, streaming FIR) + forward FFT -> Fhat.
// h and f live inside the FFT exchange buffer (overlaid; freed before FFT).
// ---------------------------------------------------------------------------
__global__ __launch_bounds__(256, 4) void fft_filter_kernel() {
    __shared__ ull exch[16 * PITCH];
    __shared__ float sgs[64];
    float* hs = (float*)exch;        // h_0..2047  (first 8KB of exch)
    float* sf = hs + SEQ;            // f_0..2047  (next 8KB)
    const int tid = threadIdx.x;
    const int h   = blockIdx.x;

    #pragma unroll
    for (int q = 0; q < 8; q++)
        hs[tid + 256 * q] = d_h[h * SEQ + tid + 256 * q];
    if (tid < 64) sgs[tid] = d_g[h * NK + tid];
    __syncthreads();

    // streaming FIR: outputs t = 8*tid .. 8*tid+7
    {
        const int t0 = tid * 8;
        float acc[8];
        #pragma unroll
        for (int k = 0; k < 8; k++) acc[k] = 0.f;
        #pragma unroll
        for (int ic = 0; ic < 8; ic++) {
            float w[15];
            const int base = t0 - 8 * ic - 7;
            #pragma unroll
            for (int d = 0; d < 15; d++) {
                const int idx = base + d;
                w[d] = (idx >= 0) ? hs[idx] : 0.f;
            }
            #pragma unroll
            for (int j = 0; j < 8; j++) {
                const float g = sgs[8 * ic + j];
                #pragma unroll
                for (int k = 0; k < 8; k++)
                    acc[k] += g * w[7 + k - j];
            }
        }
        __syncthreads();                  // all hs reads done before sf aliasing concerns
        #pragma unroll
        for (int k = 0; k < 8; k++) sf[t0 + k] = acc[k];
    }
    __syncthreads();

    ull rg[16];
    #pragma unroll
    for (int q = 0; q < 8; q++)
        rg[q] = pk2(sf[tid + 256 * q], 0.f);
    __syncthreads();                      // before FFT overwrites exch

    fft4096_fwd(rg, exch, tid);

    #pragma unroll
    for (int q = 0; q < 16; q++)
        d_Fhat[(size_t)h * NFFT + q * 256 + tid] = rg[q];
}

// ---------------------------------------------------------------------------
// K3: FFT convolution, two batches packed per complex FFT.  (unchanged)
// ---------------------------------------------------------------------------
__global__ __launch_bounds__(256, 4) void conv_kernel(const float* __restrict__ u,
                                                      float* __restrict__ y) {
    __shared__ ull exch[16 * PITCH];
    ull r[16];
    const int t  = threadIdx.x;
    const int h  = blockIdx.y;
    const int bp = blockIdx.x;
    const float* u0 = u + ((size_t)(2 * bp) * NHEADS + h) * SEQ;
    const float* u1 = u0 + (size_t)NHEADS * SEQ;

    #pragma unroll
    for (int q = 0; q < 8; q++) {
        int idx = t + 256 * q;
        r[q] = pk2(__ldg(&u0[idx]), __ldg(&u1[idx]));
    }

    fft4096_fwd(r, exch, t);

    const ull* Fh = d_Fhat + (size_t)h * NFFT;
    #pragma unroll
    for (int q = 0; q < 16; q++) {
        float fx, fy; unpk2(__ldg(&Fh[q * 256 + t]), fx, fy);
        r[q] = pcmulf(r[q], fx, fy);
    }

    fft4096_inv(r, exch, t);

    float* y0 = y + ((size_t)(2 * bp) * NHEADS + h) * SEQ;
    float* y1 = y0 + (size_t)NHEADS * SEQ;
    #pragma unroll
    for (int m = 0; m < 8; m++) {
        int idx = t + 256 * m;
        float a, b; unpk2(r[m], a, b);
        y0[idx] = a;
        y1[idx] = b;
    }
}

// ---------------------------------------------------------------------------
extern "C" void kernel_launch(void* const* d_in, const int* in_sizes, int n_in,
                              void* d_out, int out_size) {
    const float* u = (const float*)d_in[0];
    const float* k = (const float*)d_in[1];
    if (n_in >= 2 && in_sizes[0] < in_sizes[1]) {
        const float* t = u; u = k; k = t;
    }
    float* y = (float*)d_out;

    filter_kernel<<<NHEADS, 256>>>(k);
    fft_filter_kernel<<<NHEADS, 256>>>();
    conv_kernel<<<dim3(NB / 2, NHEADS), 256>>>(u, y);
}